// round 17
// baseline (speedup 1.0000x reference)
#include <cuda_runtime.h>
#include <cuda_bf16.h>
#include <cstdint>
#include <cstddef>
#include <cfloat>

// Problem constants (fixed by setup_inputs).
#define B_Q    256
#define N_BANK 50000
#define DIM_S  4096
#define DIM_D  2048
#define KTOP   9

// GEMM tiling: 128(M) x 256(N) x 32(K-fp32), 512 threads, 16 warps of 64x32.
#define TILE_M   128
#define TILE_N   256
#define T_STRIDE 80                 // bytes per bf16 tile row (64B data + 16B pad)
#define A_TILE   (128 * T_STRIDE)   // 10240
#define B_TILE   (256 * T_STRIDE)   // 20480
#define STAGE    (A_TILE + B_TILE)  // 30720
#define OFF_INV  (2 * STAGE)        // 61440
#define SMEM_TOTAL (OFF_INV + 1024) // 62464

// Candidate machinery (top-4 per 32-col stripe -> top-16 -> exact rescore)
#define NSTRIPE_PAD  1568           // 196 N-tiles x 8 stripes = 1568 exactly
#define NCAND        16
#define SELSZ  ((size_t)B_Q * NSTRIPE_PAD * 4)

// ---------------- static device scratch (no allocations allowed) -------------
__device__ __align__(128) float2 g_sel[2 * SELSZ];   // 25.7 MB (per-branch)

// ---------------- PTX helpers -------------------------------------------------
__device__ __forceinline__ uint32_t smem_u32(const void* p) {
    uint32_t a;
    asm("{ .reg .u64 t; cvta.to.shared.u64 t, %1; cvt.u32.u64 %0, t; }" : "=r"(a) : "l"(p));
    return a;
}
__device__ __forceinline__ void sts64(uint32_t addr, uint32_t a, uint32_t b) {
    asm volatile("st.shared.v2.b32 [%0], {%1,%2};" :: "r"(addr), "r"(a), "r"(b));
}
#define LDSM4(r, addr) \
    asm volatile("ldmatrix.sync.aligned.m8n8.x4.shared.b16 {%0,%1,%2,%3}, [%4];" \
        : "=r"((r)[0]), "=r"((r)[1]), "=r"((r)[2]), "=r"((r)[3]) : "r"(addr))

#define MMA16816(d, a, b0, b1) \
    asm volatile("mma.sync.aligned.m16n8k16.row.col.f32.bf16.bf16.f32 " \
        "{%0,%1,%2,%3}, {%4,%5,%6,%7}, {%8,%9}, {%0,%1,%2,%3};" \
        : "+f"((d)[0]), "+f"((d)[1]), "+f"((d)[2]), "+f"((d)[3]) \
        : "r"((a)[0]), "r"((a)[1]), "r"((a)[2]), "r"((a)[3]), "r"(b0), "r"(b1))

// float4 -> two packed bf16x2 (low 16 bits = lower column)
__device__ __forceinline__ void cvt_hi(float4 v, uint32_t& h0, uint32_t& h1) {
    asm("cvt.rn.bf16x2.f32 %0, %1, %2;" : "=r"(h0) : "f"(v.y), "f"(v.x));
    asm("cvt.rn.bf16x2.f32 %0, %1, %2;" : "=r"(h1) : "f"(v.w), "f"(v.z));
}
__device__ __forceinline__ float sq4(float4 a) {
    return a.x * a.x + a.y * a.y + a.z * a.z + a.w * a.w;
}

// sorted depth-4 insert (descending)
__device__ __forceinline__ void ins4(float s, int n, float* v, int* id) {
    if (s <= v[3]) return;
    v[3] = s; id[3] = n;
    for (int q = 3; q > 0; q--) {
        if (v[q] > v[q - 1]) {
            float tv = v[q]; v[q] = v[q - 1]; v[q - 1] = tv;
            int   ti = id[q]; id[q] = id[q - 1]; id[q - 1] = ti;
        } else break;
    }
}
__device__ __forceinline__ void ins_n(float s, int n, float* v, int* id, int depth) {
    if (s <= v[depth - 1]) return;
    v[depth - 1] = s; id[depth - 1] = n;
    for (int q = depth - 1; q > 0; q--) {
        if (v[q] > v[q - 1]) {
            float tv = v[q]; v[q] = v[q - 1]; v[q - 1] = tv;
            int   ti = id[q]; id[q] = id[q - 1]; id[q - 1] = ti;
        } else break;
    }
}

// one k16-step of the 64x32 warp-tile MMA
#define DO_KC(kc) { \
    uint32_t ah[4][4], bh[2][4]; \
    _Pragma("unroll") \
    for (int mi = 0; mi < 4; mi++) \
        LDSM4(ah[mi], at + (uint32_t)(mi * 16 * T_STRIDE) + a_colk + (kc) * 32); \
    LDSM4(bh[0], bt + (kc) * 32); \
    LDSM4(bh[1], bt + (kc) * 32 + 16); \
    _Pragma("unroll") \
    for (int mi = 0; mi < 4; mi++) \
        _Pragma("unroll") \
        for (int ni = 0; ni < 4; ni++) \
            MMA16816(acc[mi][ni], ah[mi], bh[0][ni], bh[1][ni]); \
}

// ---------------- 0) zero the output (atomic accumulation target) -------------
__global__ void zero_out_kernel(float* __restrict__ out) {
    out[threadIdx.x] = 0.f;
}

// ---------------- 1) 1-pass bf16 HMMA GEMM, both branches in one launch -------
__global__ __launch_bounds__(512, 1)
void gemm_hmma_kernel(const float* __restrict__ fc, const float* __restrict__ sem,
                      const float* __restrict__ fd, const float* __restrict__ dst)
{
    extern __shared__ char smem[];
    const uint32_t sb = smem_u32(smem);
    const int br = blockIdx.z;
    const float* __restrict__ A    = br ? fd  : fc;
    const float* __restrict__ Bank = br ? dst : sem;
    const int K = br ? DIM_D : DIM_S;
    float2* __restrict__ selb = g_sel + (size_t)br * SELSZ;

    const int tid = threadIdx.x;
    const int w = tid >> 5, l = tid & 31;
    const int wm = w >> 3, wn = w & 7;           // warp grid 2 x 8 (64x32 tiles)
    const int m0 = blockIdx.x * TILE_M;
    const int n0 = blockIdx.y * TILE_N;
    const int NC = K >> 5;

    // ---- coalesced loader: 8 threads/row, one float4 each; A 2 + B 4 groups --
    const int c8 = tid & 7;
    const int r0 = tid >> 3;                     // 0..63
    const float* Agp = A + (size_t)(m0 + r0) * K + c8 * 4;
    const float* Bgp = Bank + (size_t)(n0 + r0) * K + c8 * 4;   // n0+r0 < N_BANK always
    const size_t rstep = (size_t)64 * K;
    bool bok[4];
    #pragma unroll
    for (int it = 0; it < 4; it++) bok[it] = (n0 + r0 + 64 * it) < N_BANK;
    const uint32_t sts_off = (uint32_t)(r0 * T_STRIDE + c8 * 8);

    // ---- ldmatrix lane bases ----------------------------------------------------
    const uint32_t a_base = (uint32_t)((wm * 64 + (l & 15)) * T_STRIDE);
    const uint32_t a_colk = (uint32_t)((l >> 4) << 4);
    const uint32_t b_base = (uint32_t)((wn * 32 + l) * T_STRIDE);

    float acc[4][4][4];
    #pragma unroll
    for (int i = 0; i < 4; i++)
        #pragma unroll
        for (int j = 0; j < 4; j++)
            #pragma unroll
            for (int e = 0; e < 4; e++) acc[i][j][e] = 0.f;

    float bsum[4] = {0.f, 0.f, 0.f, 0.f};

    // ---- prologue: chunk 0 -> stage 0 ---------------------------------------------
    {
        #pragma unroll
        for (int it = 0; it < 2; it++) {
            float4 v = *reinterpret_cast<const float4*>(Agp + it * rstep);
            uint32_t h0, h1; cvt_hi(v, h0, h1);
            sts64(sb + sts_off + (uint32_t)(it * 64 * T_STRIDE), h0, h1);
        }
        #pragma unroll
        for (int it = 0; it < 4; it++) {
            float4 v = bok[it] ? *reinterpret_cast<const float4*>(Bgp + it * rstep)
                               : make_float4(0.f, 0.f, 0.f, 0.f);
            bsum[it] += sq4(v);
            uint32_t h0, h1; cvt_hi(v, h0, h1);
            sts64(sb + A_TILE + sts_off + (uint32_t)(it * 64 * T_STRIDE), h0, h1);
        }
    }
    __syncthreads();

    // ---- main loop --------------------------------------------------------------
    #pragma unroll 1
    for (int ch = 0; ch < NC; ch++) {
        const uint32_t stc = sb + (uint32_t)(ch & 1) * STAGE;
        const uint32_t stn = sb + (uint32_t)((ch + 1) & 1) * STAGE;
        const uint32_t at = stc + a_base;
        const uint32_t bt = stc + A_TILE + b_base;
        const bool pf = (ch + 1) < NC;
        const int k1 = (ch + 1) << 5;

        // prefetch next chunk (A 2 + B 4 float4), overlapping the MMA block
        float4 av[2], bv[4];
        if (pf) {
            #pragma unroll
            for (int it = 0; it < 2; it++)
                av[it] = *reinterpret_cast<const float4*>(Agp + k1 + it * rstep);
            #pragma unroll
            for (int it = 0; it < 4; it++)
                bv[it] = bok[it] ? *reinterpret_cast<const float4*>(Bgp + k1 + it * rstep)
                                 : make_float4(0.f, 0.f, 0.f, 0.f);
        }

        DO_KC(0)

        if (pf) {
            #pragma unroll
            for (int it = 0; it < 2; it++) {
                uint32_t h0, h1; cvt_hi(av[it], h0, h1);
                sts64(stn + sts_off + (uint32_t)(it * 64 * T_STRIDE), h0, h1);
            }
            #pragma unroll
            for (int it = 0; it < 4; it++) {
                bsum[it] += sq4(bv[it]);
                uint32_t h0, h1; cvt_hi(bv[it], h0, h1);
                sts64(stn + A_TILE + sts_off + (uint32_t)(it * 64 * T_STRIDE), h0, h1);
            }
        }

        DO_KC(1)

        __syncthreads();
    }

    // ---- per-row inverse norms (8 lanes per row: xor 1,2,4) -----------------------
    float* s_inv = reinterpret_cast<float*>(smem + OFF_INV);
    #pragma unroll
    for (int it = 0; it < 4; it++) {
        float v = bsum[it];
        v += __shfl_xor_sync(0xffffffffu, v, 1);
        v += __shfl_xor_sync(0xffffffffu, v, 2);
        v += __shfl_xor_sync(0xffffffffu, v, 4);
        if (c8 == 0)
            s_inv[r0 + 64 * it] = (v > 0.f) ? rsqrtf(v) : 0.f;
    }
    __syncthreads();

    // ---- epilogue: per-(row, 32-col stripe) top-4 of scaled scores ----------------
    {
        const int qr = l >> 2;
        const int qc = (l & 3) * 2;
        const int stripe = blockIdx.y * 8 + wn;
        #pragma unroll
        for (int mi = 0; mi < 4; mi++) {
            #pragma unroll
            for (int h = 0; h < 2; h++) {
                float v[4]; int id[4];
                #pragma unroll
                for (int j = 0; j < 4; j++) { v[j] = -FLT_MAX; id[j] = 0; }
                #pragma unroll
                for (int ni = 0; ni < 4; ni++) {
                    const int nloc = wn * 32 + ni * 8 + qc;
                    const int ng = n0 + nloc;
                    const float* d = acc[mi][ni];
                    float s0 = (ng     < N_BANK) ? d[2 * h]     * s_inv[nloc]     : -FLT_MAX;
                    float s1 = (ng + 1 < N_BANK) ? d[2 * h + 1] * s_inv[nloc + 1] : -FLT_MAX;
                    ins4(s0, ng,     v, id);
                    ins4(s1, ng + 1, v, id);
                }
                #pragma unroll
                for (int o = 1; o <= 2; o <<= 1) {
                    float tv[4]; int ti[4];
                    #pragma unroll
                    for (int j = 0; j < 4; j++) { tv[j] = v[j]; ti[j] = id[j]; }
                    #pragma unroll
                    for (int j = 0; j < 4; j++) {
                        float ov = __shfl_xor_sync(0xffffffffu, tv[j], o);
                        int   oi = __shfl_xor_sync(0xffffffffu, ti[j], o);
                        ins4(ov, oi, v, id);
                    }
                }
                if ((l & 3) == 0) {
                    const int row = m0 + wm * 64 + mi * 16 + qr + 8 * h;
                    float2* dp = selb + ((size_t)row * NSTRIPE_PAD + stripe) * 4;
                    #pragma unroll
                    for (int j = 0; j < 4; j++)
                        dp[j] = make_float2(v[j], __int_as_float(id[j]));
                }
            }
        }
    }
}

// ---------------- 2) finalsel: 256 threads, grid (row, branch), atomic combine -
__global__ __launch_bounds__(256)
void finalsel_kernel(const float* __restrict__ fc, const float* __restrict__ sem,
                     const float* __restrict__ fd, const float* __restrict__ dst,
                     const float* __restrict__ metrics,
                     float* __restrict__ out)
{
    __shared__ float sv[256 * 4];
    __shared__ int   si[256 * 4];
    __shared__ float sv2[32 * 8];
    __shared__ int   si2[32 * 8];
    __shared__ int   ci[NCAND];
    __shared__ float ss[NCAND];

    const int row = blockIdx.x;
    const int br  = blockIdx.y;
    const int tid = threadIdx.x;

    const float* Aq   = br ? fd  : fc;
    const float* Bank = br ? dst : sem;
    const int K = br ? DIM_D : DIM_S;
    const float4* base4 = reinterpret_cast<const float4*>(
        g_sel + (size_t)br * SELSZ + (size_t)row * NSTRIPE_PAD * 4);
    const int nf4 = NSTRIPE_PAD * 4 / 2;      // 3136

    // phase 1: per-thread top-4 with two independent chains (MLP=2)
    float va[4], vb[4]; int ia[4], ib[4];
    #pragma unroll
    for (int j = 0; j < 4; j++) { va[j] = vb[j] = -FLT_MAX; ia[j] = ib[j] = 0; }
    for (int i = tid; i < nf4; i += 512) {
        float4 x = base4[i];
        const bool g2 = (i + 256) < nf4;
        float4 y = g2 ? base4[i + 256] : make_float4(-FLT_MAX, 0.f, -FLT_MAX, 0.f);
        ins4(x.x, __float_as_int(x.y), va, ia);
        ins4(x.z, __float_as_int(x.w), va, ia);
        ins4(y.x, __float_as_int(y.y), vb, ib);
        ins4(y.z, __float_as_int(y.w), vb, ib);
    }
    #pragma unroll
    for (int j = 0; j < 4; j++) ins4(vb[j], ib[j], va, ia);
    #pragma unroll
    for (int j = 0; j < 4; j++) { sv[tid * 4 + j] = va[j]; si[tid * 4 + j] = ia[j]; }
    __syncthreads();

    // phase 2: warp-0 funnel 1024 -> 256
    if (tid < 32) {
        float mv[8]; int mi[8];
        #pragma unroll
        for (int j = 0; j < 8; j++) { mv[j] = -FLT_MAX; mi[j] = 0; }
        for (int e = tid; e < 1024; e += 32)
            ins_n(sv[e], si[e], mv, mi, 8);
        #pragma unroll
        for (int j = 0; j < 8; j++) { sv2[tid * 8 + j] = mv[j]; si2[tid * 8 + j] = mi[j]; }
    }
    __syncthreads();

    // phase 3: thread 0 -> top-16 candidates
    if (tid == 0) {
        float mv[NCAND]; int mi[NCAND];
        #pragma unroll
        for (int j = 0; j < NCAND; j++) { mv[j] = -FLT_MAX; mi[j] = 0; }
        for (int e = 0; e < 256; e++)
            ins_n(sv2[e], si2[e], mv, mi, NCAND);
        #pragma unroll
        for (int j = 0; j < NCAND; j++) ci[j] = mi[j];
    }
    __syncthreads();

    // phase 4: exact fp32 rescore (2 candidates per warp, MLP=2 inner)
    {
        const int wp = tid >> 5, l = tid & 31;
        const float4* q4 = reinterpret_cast<const float4*>(Aq + (size_t)row * K);
        const int kv = K >> 2;
        for (int c = wp; c < NCAND; c += 8) {
            const int idx = ci[c];
            const float4* b4 = reinterpret_cast<const float4*>(Bank + (size_t)idx * K);
            float d0 = 0.f, s0 = 0.f, d1 = 0.f, s1 = 0.f;
            for (int i = l; i < kv; i += 64) {
                float4 b = b4[i], q = q4[i];
                float4 b2, q2;
                const bool g2 = (i + 32) < kv;
                if (g2) { b2 = b4[i + 32]; q2 = q4[i + 32]; }
                d0 += q.x * b.x + q.y * b.y + q.z * b.z + q.w * b.w;
                s0 += b.x * b.x + b.y * b.y + b.z * b.z + b.w * b.w;
                if (g2) {
                    d1 += q2.x * b2.x + q2.y * b2.y + q2.z * b2.z + q2.w * b2.w;
                    s1 += b2.x * b2.x + b2.y * b2.y + b2.z * b2.z + b2.w * b2.w;
                }
            }
            float dot = d0 + d1, bsq = s0 + s1;
            #pragma unroll
            for (int o = 16; o; o >>= 1) {
                dot += __shfl_xor_sync(0xffffffffu, dot, o);
                bsq += __shfl_xor_sync(0xffffffffu, bsq, o);
            }
            if (l == 0) ss[c] = dot * rsqrtf(bsq);
        }
    }
    __syncthreads();

    // phase 5: exact top-9 + metrics sum, atomically combined across branches
    if (tid == 0) {
        float v9[KTOP]; int id9[KTOP];
        #pragma unroll
        for (int j = 0; j < KTOP; j++) { v9[j] = -FLT_MAX; id9[j] = 0; }
        #pragma unroll
        for (int c = 0; c < NCAND; c++)
            ins_n(ss[c], ci[c], v9, id9, KTOP);
        float ssum = 0.f;
        #pragma unroll
        for (int j = 0; j < KTOP; j++) ssum += metrics[id9[j]];
        // fp add is commutative -> order of the two atomics doesn't change bits
        atomicAdd(&out[row], ssum * (1.f / (2.f * KTOP)));
    }
}

// ---------------- launch ------------------------------------------------------
extern "C" void kernel_launch(void* const* d_in, const int* in_sizes, int n_in,
                              void* d_out, int out_size) {
    const float* f_content    = nullptr;
    const float* f_distorsion = nullptr;
    const float* sem_bank     = nullptr;
    const float* dst_bank     = nullptr;
    const float* metrics      = nullptr;
    for (int i = 0; i < n_in; i++) {
        switch (in_sizes[i]) {
            case B_Q * DIM_S:    f_content    = (const float*)d_in[i]; break;
            case B_Q * DIM_D:    f_distorsion = (const float*)d_in[i]; break;
            case N_BANK * DIM_S: sem_bank     = (const float*)d_in[i]; break;
            case N_BANK * DIM_D: dst_bank     = (const float*)d_in[i]; break;
            case N_BANK:         metrics      = (const float*)d_in[i]; break;
            default: break; // scalar K (=9) compiled in
        }
    }
    float* out = (float*)d_out;

    cudaFuncSetAttribute(gemm_hmma_kernel,
                         cudaFuncAttributeMaxDynamicSharedMemorySize, SMEM_TOTAL);

    zero_out_kernel<<<1, B_Q>>>(out);

    // x = M (fastest, L2-shares B stripe), y = N, z = branch
    dim3 grid(B_Q / TILE_M, (N_BANK + TILE_N - 1) / TILE_N, 2);   // (2, 196, 2)
    gemm_hmma_kernel<<<grid, 512, SMEM_TOTAL>>>(f_content, sem_bank,
                                                f_distorsion, dst_bank);

    dim3 fgrid(B_Q, 2);
    finalsel_kernel<<<fgrid, 256>>>(f_content, sem_bank, f_distorsion, dst_bank,
                                    metrics, out);
}